// round 15
// baseline (speedup 1.0000x reference)
#include <cuda_runtime.h>
#include <cuda_bf16.h>
#include <math.h>

#define NN 100000
#define NE 600000
#define HH 128
#define LL 5
#define GG 512
#define BN_EPS 1e-5f
#define PCHUNK 100   // nodes per warp in pool kernel (NN/PCHUNK = 1000 warps)
#define NB_AGG (NN / 8)   // 12500 blocks, exact (no tail warp)

// ---------------- device scratch (no runtime allocation allowed) ----------------
__device__ float d_h[NN * HH];     // node features (pre-BN at layer boundary)
__device__ float d_ht[NN * HH];    // h @ W
__device__ float d_agg[NN * HH];   // aggregated messages
__device__ int   d_cnt[NN];        // in-degree (excluding self loop)
__device__ float d_dis[NN];        // rsqrt(deg) with self loop
__device__ int   d_rowptr[NN + 1];
__device__ int   d_cursor[NN];
__device__ int2  d_csr[NE];        // packed {src, __float_as_int(w)} -> one LDG.64/edge
__device__ int   d_bsums[128];     // scan block sums
__device__ float d_bnsum[HH];
__device__ float d_bnsq[HH];
__device__ float d_scale[HH];      // gamma * rsqrt(var+eps)
__device__ float d_shift[HH];      // beta - mu * scale
__device__ float d_gsum[GG * HH];
__device__ float d_gcnt[GG];
__device__ unsigned d_Whi[LL * HH * HH];  // per-layer W split into tf32 hi/lo
__device__ unsigned d_Wlo[LL * HH * HH];
__device__ int   d_aggdone = 0;    // threadfence-reduction completion counter

__constant__ int c_off[9] = {0, 119, 123, 135, 147, 157, 163, 169, 171};

// ---------------- atom encoder: h[i,:] = sum_f table[x[i,f]+off[f], :] --------
// Also zeroes d_cnt (consumed by degcount, stream-ordered after) and the pool
// accumulators d_gsum/d_gcnt (consumed only by pool_kernel at the very end) --
// folds the former zero_cnt_kernel and zero_pool_kernel launches.
__global__ void encode_kernel(const int* __restrict__ x, const float* __restrict__ table) {
    int gt = blockIdx.x * 256 + threadIdx.x;   // 3.2M threads total
    if (gt < NN) d_cnt[gt] = 0;
    if (gt < GG * HH) d_gsum[gt] = 0.f;
    if (gt < GG) d_gcnt[gt] = 0.f;

    int node = blockIdx.x * 8 + (threadIdx.x >> 5);
    int lane = threadIdx.x & 31;
    if (node >= NN) return;
    float4 acc = make_float4(0.f, 0.f, 0.f, 0.f);
#pragma unroll
    for (int f = 0; f < 9; f++) {
        int row = __ldg(&x[node * 9 + f]) + c_off[f];
        float4 v = *(const float4*)&table[row * HH + lane * 4];
        acc.x += v.x; acc.y += v.y; acc.z += v.z; acc.w += v.w;
    }
    *(float4*)&d_h[node * HH + lane * 4] = acc;
}

// ---------------- CSR construction ----------------
__global__ void degcount_kernel(const int* __restrict__ ei) {
    int e = blockIdx.x * blockDim.x + threadIdx.x;
    if (e < NE) atomicAdd(&d_cnt[ei[NE + e]], 1);
}

// scan1: per-block (1024 elems) inclusive scan of d_cnt -> d_rowptr, totals -> d_bsums
__global__ void scan1_kernel() {
    __shared__ int sh[256];
    int b = blockIdx.x;
    int base = b * 1024;
    int t = threadIdx.x;
    int v[4];
    int s = 0;
#pragma unroll
    for (int i = 0; i < 4; i++) {
        int idx = base + t * 4 + i;
        v[i] = (idx < NN) ? d_cnt[idx] : 0;
        s += v[i];
    }
    sh[t] = s;
    __syncthreads();
#pragma unroll
    for (int off = 1; off < 256; off <<= 1) {
        int x = (t >= off) ? sh[t - off] : 0;
        __syncthreads();
        sh[t] += x;
        __syncthreads();
    }
    int run = (t > 0) ? sh[t - 1] : 0;
#pragma unroll
    for (int i = 0; i < 4; i++) {
        run += v[i];
        int idx = base + t * 4 + i;
        if (idx < NN) d_rowptr[idx] = run;  // per-block inclusive
    }
    if (t == 255) d_bsums[b] = sh[255];
}

// scan2: exclusive scan of block sums (nb <= 128), single block of 128 threads
__global__ void scan2_kernel(int nb) {
    __shared__ int sh[128];
    int t = threadIdx.x;
    int v = (t < nb) ? d_bsums[t] : 0;
    sh[t] = v;
    __syncthreads();
#pragma unroll
    for (int off = 1; off < 128; off <<= 1) {
        int x = (t >= off) ? sh[t - off] : 0;
        __syncthreads();
        sh[t] += x;
        __syncthreads();
    }
    if (t < nb) d_bsums[t] = sh[t] - v;  // exclusive
}

// scan3: finalize exclusive rowptr, init cursor, compute dis
__global__ void scan3_kernel() {
    int i = blockIdx.x * blockDim.x + threadIdx.x;
    if (i < NN) {
        int b = i >> 10;
        int excl = d_rowptr[i] - d_cnt[i] + d_bsums[b];
        d_rowptr[i] = excl;
        d_cursor[i] = excl;
        d_dis[i] = rsqrtf((float)(d_cnt[i] + 1));  // +1 self loop
    }
    if (i == 0) d_rowptr[NN] = NE;
}

__global__ void fill_kernel(const int* __restrict__ ei) {
    int e = blockIdx.x * blockDim.x + threadIdx.x;
    if (e < NE) {
        int r = ei[e];
        int c = ei[NE + e];
        int p = atomicAdd(&d_cursor[c], 1);
        d_csr[p] = make_int2(r, __float_as_int(d_dis[r] * d_dis[c]));
    }
}

// ---------------- TF32 helpers ----------------
__device__ __forceinline__ unsigned f2tf32(float x) {
    unsigned r;
    asm("cvt.rna.tf32.f32 %0, %1;" : "=r"(r) : "f"(x));
    return r;
}

// one-shot: split all 5 layers' W into tf32 hi/lo (x = hi + lo to ~2^-24 rel)
__global__ void wsplit_kernel(const float* __restrict__ convW) {
    int i = blockIdx.x * blockDim.x + threadIdx.x;
    if (i >= LL * HH * HH) return;
    float w = convW[i];
    unsigned hi = f2tf32(w);
    d_Whi[i] = hi;
    d_Wlo[i] = f2tf32(w - __uint_as_float(hi));
}

// D(16x8) += A(16x8) * B(8x8), tf32 inputs, f32 accum.
// A row-major, B col-major (B[k][n] with b0=(k=tig,n=g), b1=(k=tig+4,n=g)).
__device__ __forceinline__ void mma_tf32(float* d, const unsigned* a, const unsigned* b) {
    asm volatile(
        "mma.sync.aligned.m16n8k8.row.col.f32.tf32.tf32.f32 "
        "{%0,%1,%2,%3}, {%4,%5,%6,%7}, {%8,%9}, {%0,%1,%2,%3};"
        : "+f"(d[0]), "+f"(d[1]), "+f"(d[2]), "+f"(d[3])
        : "r"(a[0]), "r"(a[1]), "r"(a[2]), "r"(a[3]), "r"(b[0]), "r"(b[1]));
}

// ---------------- GEMM (3xTF32 tensor cores + fused BN apply) ----------------
// d_ht[NN,128] = A[NN,128] * W_l[128,128], where
//   apply_bn==0: A = d_h (raw encoder output)
//   apply_bn==1: A = relu(fma(d_agg, scale, shift)) + d_h, also stored to d_h.
// 3xTF32 split: x = hi + lo (hi = rna-tf32(x), lo = rna-tf32(x - hi));
// D = ah*bh + ah*bl + al*bh  (al*bl ~2^-24 rel, dropped) -> fp32-grade result.
// W is pre-split by wsplit_kernel; A split happens in-kernel (data-dependent).
// Block 0 also zeroes the BN stat accumulators for the FOLLOWING agg_kernel
// (stream order guarantees gemm completes before agg's atomics start).
// Warp grid 4(m) x 2(n): each warp owns 32 rows x 64 cols = 2x8 m16n8 tiles.
// Double-buffered staging: writes to buf (c+1)&1 are ordered after the barrier
// of iteration c-1, which postdates all reads of that buffer -> race-free with
// one sync per chunk.
__global__ __launch_bounds__(256, 2) void gemm_kernel(int layer, int apply_bn) {
    __shared__ unsigned As_hi[2][8][136];   // [buf][k][row]  (136: 8*tig+g mod 32 bijective)
    __shared__ unsigned As_lo[2][8][136];
    __shared__ unsigned Ws_hi[2][8][132];   // [buf][k][n]
    __shared__ unsigned Ws_lo[2][8][132];

    const unsigned* __restrict__ Whi = d_Whi + layer * HH * HH;
    const unsigned* __restrict__ Wlo = d_Wlo + layer * HH * HH;

    int t = threadIdx.x;
    if (blockIdx.x == 0 && t < HH) {   // fold former zero_stats_kernel
        d_bnsum[t] = 0.f;
        d_bnsq[t] = 0.f;
    }
    int rowBase = blockIdx.x * 128;
    int warp = t >> 5;
    int lane = t & 31;
    int g   = lane >> 2;      // groupID
    int tig = lane & 3;       // thread-in-group
    int wm = warp & 3;        // m-position (32 rows each)
    int wn = warp >> 2;       // n-position (64 cols each)

    // staging coords
    int r  = t >> 1;              // row this thread stages
    int kq = (t & 1) * 4;         // k-quad within 8-wide chunk
    int grow = rowBase + r;
    bool rowOK = (grow < NN);
    int wk = t >> 5;              // W staging: k row
    int wn4 = (t & 31) * 4;       // W staging: n start (uint4)

    float acc[2][8][4];
#pragma unroll
    for (int mt = 0; mt < 2; mt++)
#pragma unroll
        for (int nt = 0; nt < 8; nt++)
#pragma unroll
            for (int i = 0; i < 4; i++) acc[mt][nt][i] = 0.f;

    // ---- fetch chunk k0 operands (global -> regs), BN fused ----
    auto load_chunk = [&](int k0, float4& va, uint4& whi, uint4& wlo) {
        va = make_float4(0.f, 0.f, 0.f, 0.f);
        if (rowOK) {
            int gidx = grow * 128 + k0 + kq;
            if (apply_bn) {
                float4 aa = *(const float4*)&d_agg[gidx];
                float4 hh = *(const float4*)&d_h[gidx];
                int c = k0 + kq;
                va.x = fmaxf(fmaf(aa.x, d_scale[c + 0], d_shift[c + 0]), 0.f) + hh.x;
                va.y = fmaxf(fmaf(aa.y, d_scale[c + 1], d_shift[c + 1]), 0.f) + hh.y;
                va.z = fmaxf(fmaf(aa.z, d_scale[c + 2], d_shift[c + 2]), 0.f) + hh.z;
                va.w = fmaxf(fmaf(aa.w, d_scale[c + 3], d_shift[c + 3]), 0.f) + hh.w;
                *(float4*)&d_h[gidx] = va;   // persist full-fp32 for next residual (once per elem)
            } else {
                va = *(const float4*)&d_h[gidx];
            }
        }
        int widx = (k0 + wk) * 128 + wn4;
        whi = *(const uint4*)&Whi[widx];
        wlo = *(const uint4*)&Wlo[widx];
    };
    // ---- A hi/lo split + store to smem; W stored pre-split ----
    auto store_chunk = [&](int buf, const float4& va, const uint4& whi, const uint4& wlo) {
        float av[4] = {va.x, va.y, va.z, va.w};
#pragma unroll
        for (int i = 0; i < 4; i++) {
            unsigned hi = f2tf32(av[i]);
            As_hi[buf][kq + i][r] = hi;
            As_lo[buf][kq + i][r] = f2tf32(av[i] - __uint_as_float(hi));
        }
        *(uint4*)&Ws_hi[buf][wk][wn4] = whi;   // row stride 132*4=528B (16B aligned)
        *(uint4*)&Ws_lo[buf][wk][wn4] = wlo;
    };

    // prologue: chunk 0 -> buf 0
    float4 va; uint4 whi, wlo;
    load_chunk(0, va, whi, wlo);
    store_chunk(0, va, whi, wlo);
    __syncthreads();

    for (int c = 0; c < 16; c++) {
        float4 nva; uint4 nwhi, nwlo;
        if (c < 15) load_chunk((c + 1) * 8, nva, nwhi, nwlo);  // prefetch next chunk
        int buf = c & 1;

        // A fragments for both m-tiles (m16n8k8 layout:
        // a0=(g,tig) a1=(g+8,tig) a2=(g,tig+4) a3=(g+8,tig+4))
        unsigned ah[2][4], al[2][4];
#pragma unroll
        for (int mt = 0; mt < 2; mt++) {
            int row = wm * 32 + mt * 16 + g;
            ah[mt][0] = As_hi[buf][tig][row];
            ah[mt][1] = As_hi[buf][tig][row + 8];
            ah[mt][2] = As_hi[buf][tig + 4][row];
            ah[mt][3] = As_hi[buf][tig + 4][row + 8];
            al[mt][0] = As_lo[buf][tig][row];
            al[mt][1] = As_lo[buf][tig][row + 8];
            al[mt][2] = As_lo[buf][tig + 4][row];
            al[mt][3] = As_lo[buf][tig + 4][row + 8];
        }
#pragma unroll
        for (int nt = 0; nt < 8; nt++) {
            int col = wn * 64 + nt * 8 + g;
            unsigned bh[2], bl[2];
            bh[0] = Ws_hi[buf][tig][col];
            bh[1] = Ws_hi[buf][tig + 4][col];
            bl[0] = Ws_lo[buf][tig][col];
            bl[1] = Ws_lo[buf][tig + 4][col];
#pragma unroll
            for (int mt = 0; mt < 2; mt++) {
                mma_tf32(acc[mt][nt], ah[mt], bh);
                mma_tf32(acc[mt][nt], ah[mt], bl);
                mma_tf32(acc[mt][nt], al[mt], bh);
            }
        }
        if (c < 15) {
            store_chunk((c + 1) & 1, nva, nwhi, nwlo);
            __syncthreads();
        }
    }

    // epilogue: c0=(g, tig*2) c1=(g, tig*2+1) c2=(g+8, tig*2) c3=(g+8, tig*2+1)
#pragma unroll
    for (int mt = 0; mt < 2; mt++) {
        int r0 = rowBase + wm * 32 + mt * 16 + g;
        int r1 = r0 + 8;
#pragma unroll
        for (int nt = 0; nt < 8; nt++) {
            int col = wn * 64 + nt * 8 + tig * 2;
            if (r0 < NN)
                *(float2*)&d_ht[r0 * 128 + col] = make_float2(acc[mt][nt][0], acc[mt][nt][1]);
            if (r1 < NN)
                *(float2*)&d_ht[r1 * 128 + col] = make_float2(acc[mt][nt][2], acc[mt][nt][3]);
        }
    }
}

// ---- aggregation + fused BN stats + fused BN-prep (last block) --------------
// agg[v] = ht[v]*dis[v]^2 + sum_in ht[src]*w. Packed CSR: one LDG.64 per edge.
// 4-way edge unroll -> per-warp MLP ~6 in the dominant loop.
// After the block's global stat atomics, a threadfence-reduction elects the
// LAST-finishing block to compute d_scale/d_shift (former bnprep_kernel):
// __threadfence orders each block's atomics before its counter bump, so the
// last block reads fully-summed d_bnsum/d_bnsq. Counter self-resets -> graph
// replays stay deterministic. conv bias cancels under training-mode BN.
// NOTE: grid is exactly NN/8 blocks * 8 warps -> every warp owns a valid node.
__global__ __launch_bounds__(256) void agg_kernel(const float* __restrict__ gamma,
                                                  const float* __restrict__ beta) {
    __shared__ float sh_sum[128];
    __shared__ float sh_sq[128];
    __shared__ bool sh_last;
    int t = threadIdx.x;
    if (t < 128) { sh_sum[t] = 0.f; sh_sq[t] = 0.f; }
    __syncthreads();

    int v = blockIdx.x * 8 + (t >> 5);
    int lane = t & 31;
    float d = d_dis[v];
    float sn = d * d;
    float4 self = *(const float4*)&d_ht[v * HH + lane * 4];
    float4 acc = make_float4(self.x * sn, self.y * sn, self.z * sn, self.w * sn);
    int s = d_rowptr[v], e = d_rowptr[v + 1];
    int j = s;
    for (; j + 3 < e; j += 4) {
        int2 e0 = d_csr[j];
        int2 e1 = d_csr[j + 1];
        int2 e2 = d_csr[j + 2];
        int2 e3 = d_csr[j + 3];
        float4 x0 = *(const float4*)&d_ht[e0.x * HH + lane * 4];
        float4 x1 = *(const float4*)&d_ht[e1.x * HH + lane * 4];
        float4 x2 = *(const float4*)&d_ht[e2.x * HH + lane * 4];
        float4 x3 = *(const float4*)&d_ht[e3.x * HH + lane * 4];
        float w0 = __int_as_float(e0.y);
        float w1 = __int_as_float(e1.y);
        float w2 = __int_as_float(e2.y);
        float w3 = __int_as_float(e3.y);
        acc.x = fmaf(x0.x, w0, acc.x); acc.y = fmaf(x0.y, w0, acc.y);
        acc.z = fmaf(x0.z, w0, acc.z); acc.w = fmaf(x0.w, w0, acc.w);
        acc.x = fmaf(x1.x, w1, acc.x); acc.y = fmaf(x1.y, w1, acc.y);
        acc.z = fmaf(x1.z, w1, acc.z); acc.w = fmaf(x1.w, w1, acc.w);
        acc.x = fmaf(x2.x, w2, acc.x); acc.y = fmaf(x2.y, w2, acc.y);
        acc.z = fmaf(x2.z, w2, acc.z); acc.w = fmaf(x2.w, w2, acc.w);
        acc.x = fmaf(x3.x, w3, acc.x); acc.y = fmaf(x3.y, w3, acc.y);
        acc.z = fmaf(x3.z, w3, acc.z); acc.w = fmaf(x3.w, w3, acc.w);
    }
    for (; j < e; j++) {
        int2 e0 = d_csr[j];
        float w = __int_as_float(e0.y);
        float4 xv = *(const float4*)&d_ht[e0.x * HH + lane * 4];
        acc.x = fmaf(xv.x, w, acc.x);
        acc.y = fmaf(xv.y, w, acc.y);
        acc.z = fmaf(xv.z, w, acc.z);
        acc.w = fmaf(xv.w, w, acc.w);
    }
    *(float4*)&d_agg[v * HH + lane * 4] = acc;

    // per-block channel reduction for BN stats (8-way shared conflicts, cheap)
    int c = lane * 4;
    atomicAdd(&sh_sum[c + 0], acc.x);
    atomicAdd(&sh_sum[c + 1], acc.y);
    atomicAdd(&sh_sum[c + 2], acc.z);
    atomicAdd(&sh_sum[c + 3], acc.w);
    atomicAdd(&sh_sq[c + 0], acc.x * acc.x);
    atomicAdd(&sh_sq[c + 1], acc.y * acc.y);
    atomicAdd(&sh_sq[c + 2], acc.z * acc.z);
    atomicAdd(&sh_sq[c + 3], acc.w * acc.w);
    __syncthreads();
    if (t < 128) {
        atomicAdd(&d_bnsum[t], sh_sum[t]);
        atomicAdd(&d_bnsq[t], sh_sq[t]);
    }

    // threadfence reduction: last block computes scale/shift
    __threadfence();
    __syncthreads();
    if (t == 0) {
        int done = atomicAdd(&d_aggdone, 1);
        sh_last = (done == NB_AGG - 1);
    }
    __syncthreads();
    if (sh_last) {
        if (t < HH) {
            const float inv = 1.0f / (float)NN;
            float m = d_bnsum[t] * inv;
            float var = d_bnsq[t] * inv - m * m;
            float sc = __ldg(&gamma[t]) * rsqrtf(var + BN_EPS);
            d_scale[t] = sc;
            d_shift[t] = __ldg(&beta[t]) - m * sc;
        }
        if (t == 0) d_aggdone = 0;   // reset for next layer / next graph replay
    }
}

// ---------------- readout ----------------
// batch_idx is SORTED: warp owns PCHUNK consecutive nodes, accumulates in
// registers, flushes atomics only on graph-id change (~66x fewer atomics).
// Fuses the LAST layer's BN apply (no relu): h_final = fma(agg,scale,shift)+h.
// d_gsum/d_gcnt were zeroed by encode_kernel at the start of this replay.
__global__ __launch_bounds__(256) void pool_kernel(const int* __restrict__ batch) {
    int w = blockIdx.x * 8 + (threadIdx.x >> 5);
    int lane = threadIdx.x & 31;
    int start = w * PCHUNK;
    if (start >= NN) return;
    int end = min(start + PCHUNK, NN);
    int c = lane * 4;
    float s0 = d_scale[c + 0], s1 = d_scale[c + 1], s2 = d_scale[c + 2], s3 = d_scale[c + 3];
    float b0 = d_shift[c + 0], b1 = d_shift[c + 1], b2 = d_shift[c + 2], b3 = d_shift[c + 3];
    int cur_g = __ldg(&batch[start]);
    float4 acc = make_float4(0.f, 0.f, 0.f, 0.f);
    float cnt = 0.f;
    for (int node = start; node < end; node++) {
        int g = __ldg(&batch[node]);   // broadcast load, uniform across warp
        if (g != cur_g) {
            float* base = &d_gsum[cur_g * HH + c];
            atomicAdd(base + 0, acc.x);
            atomicAdd(base + 1, acc.y);
            atomicAdd(base + 2, acc.z);
            atomicAdd(base + 3, acc.w);
            if (lane == 0) atomicAdd(&d_gcnt[cur_g], cnt);
            acc = make_float4(0.f, 0.f, 0.f, 0.f);
            cnt = 0.f;
            cur_g = g;
        }
        int idx = node * HH + c;
        float4 aa = *(const float4*)&d_agg[idx];
        float4 hh = *(const float4*)&d_h[idx];
        acc.x += fmaf(aa.x, s0, b0) + hh.x;
        acc.y += fmaf(aa.y, s1, b1) + hh.y;
        acc.z += fmaf(aa.z, s2, b2) + hh.z;
        acc.w += fmaf(aa.w, s3, b3) + hh.w;
        cnt += 1.f;
    }
    float* base = &d_gsum[cur_g * HH + c];
    atomicAdd(base + 0, acc.x);
    atomicAdd(base + 1, acc.y);
    atomicAdd(base + 2, acc.z);
    atomicAdd(base + 3, acc.w);
    if (lane == 0) atomicAdd(&d_gcnt[cur_g], cnt);
}

__global__ void final_kernel(const float* __restrict__ linW, const float* __restrict__ linb,
                             float* __restrict__ out) {
    int g = blockIdx.x * 8 + (threadIdx.x >> 5);
    int lane = threadIdx.x & 31;
    if (g >= GG) return;
    float4 s = *(const float4*)&d_gsum[g * HH + lane * 4];
    float4 w = *(const float4*)&linW[lane * 4];
    float dot = s.x * w.x + s.y * w.y + s.z * w.z + s.w * w.w;
#pragma unroll
    for (int off = 16; off; off >>= 1) dot += __shfl_xor_sync(0xffffffff, dot, off);
    if (lane == 0) {
        float cnt = fmaxf(d_gcnt[g], 1.f);
        float z = dot / cnt + __ldg(&linb[0]);
        out[g] = 1.f / (1.f + expf(-z));
    }
}

// ---------------- launch ----------------
extern "C" void kernel_launch(void* const* d_in, const int* in_sizes, int n_in,
                              void* d_out, int out_size) {
    const int*   x     = (const int*)d_in[0];
    const int*   ei    = (const int*)d_in[1];
    const int*   batch = (const int*)d_in[2];
    const float* table = (const float*)d_in[3];
    const float* convW = (const float*)d_in[4];
    // d_in[5] = conv_b: cancels exactly under training-mode BatchNorm -> unused
    const float* gamma = (const float*)d_in[6];
    const float* beta  = (const float*)d_in[7];
    const float* linW  = (const float*)d_in[8];
    const float* linb  = (const float*)d_in[9];
    float* out = (float*)d_out;

    const int NB_NODE_W = (NN + 7) / 8;          // 12500, warp-per-node kernels
    const int NB_EDGE   = (NE + 255) / 256;      // 2344
    const int NB_SCAN   = (NN + 1023) / 1024;    // 98
    const int NB_ELEM   = (NN + 255) / 256;      // 391
    const int NB_GEMM   = (NN + 127) / 128;      // 782
    const int NB_POOL   = (NN / PCHUNK + 7) / 8; // 125

    // encoder (also zeroes d_cnt + pool accumulators) + weight split
    encode_kernel<<<NB_NODE_W, 256>>>(x, table);
    wsplit_kernel<<<(LL * HH * HH + 255) / 256, 256>>>(convW);

    // CSR build + norms
    degcount_kernel<<<NB_EDGE, 256>>>(ei);
    scan1_kernel<<<NB_SCAN, 256>>>();
    scan2_kernel<<<1, 128>>>(NB_SCAN);
    scan3_kernel<<<NB_ELEM, 256>>>();
    fill_kernel<<<NB_EDGE, 256>>>(ei);

    // GCN layers: gemm(l) fuses BN-apply of layer l-1 (relu layers only) and
    // zeroes BN stat accumulators (block 0); agg fuses BN stats + BN-prep
    // (last-block threadfence reduction); layer 4's BN-apply (no relu) is
    // fused into pool_kernel.
    for (int l = 0; l < LL; l++) {
        gemm_kernel<<<NB_GEMM, 256>>>(l, l > 0 ? 1 : 0);
        agg_kernel<<<NB_AGG, 256>>>(gamma + l * HH, beta + l * HH);
    }

    // readout (fuses layer-4 BN apply, no relu)
    pool_kernel<<<NB_POOL, 256>>>(batch);
    final_kernel<<<(GG + 7) / 8, 256>>>(linW, linb, out);
}

// round 16
// speedup vs baseline: 1.0057x; 1.0057x over previous
#include <cuda_runtime.h>
#include <cuda_bf16.h>
#include <math.h>

#define NN 100000
#define NE 600000
#define HH 128
#define LL 5
#define GG 512
#define BN_EPS 1e-5f
#define PCHUNK 100   // nodes per warp in pool kernel (NN/PCHUNK = 1000 warps)
#define NB_AGG (NN / 8)   // 12500 blocks, exact (no tail warp)

// ---------------- device scratch (no runtime allocation allowed) ----------------
__device__ float d_h[NN * HH];     // node features (pre-BN at layer boundary)
__device__ float d_ht[NN * HH];    // h @ W
__device__ float d_agg[NN * HH];   // aggregated messages
__device__ int   d_cnt[NN];        // in-degree (excluding self loop)
__device__ float d_dis[NN];        // rsqrt(deg) with self loop
__device__ int   d_rowptr[NN + 1];
__device__ int   d_cursor[NN];
__device__ int2  d_csr[NE];        // packed {src, __float_as_int(w)} -> one LDG.64/edge
__device__ int   d_bsums[128];     // scan block sums
__device__ float d_bnsum[HH];
__device__ float d_bnsq[HH];
__device__ float d_scale[HH];      // gamma * rsqrt(var+eps)
__device__ float d_shift[HH];      // beta - mu * scale
__device__ float d_gsum[GG * HH];
__device__ float d_gcnt[GG];
__device__ unsigned d_Whi[LL * HH * HH];  // per-layer W split into tf32 hi/lo
__device__ unsigned d_Wlo[LL * HH * HH];
__device__ int   d_aggdone = 0;    // threadfence-reduction completion counter

__constant__ int c_off[9] = {0, 119, 123, 135, 147, 157, 163, 169, 171};

// ---------------- atom encoder: h[i,:] = sum_f table[x[i,f]+off[f], :] --------
// Also zeroes d_cnt (consumed by degcount, stream-ordered after) and the pool
// accumulators d_gsum/d_gcnt (consumed only by pool_kernel at the very end).
__global__ void encode_kernel(const int* __restrict__ x, const float* __restrict__ table) {
    int gt = blockIdx.x * 256 + threadIdx.x;   // 3.2M threads total
    if (gt < NN) d_cnt[gt] = 0;
    if (gt < GG * HH) d_gsum[gt] = 0.f;
    if (gt < GG) d_gcnt[gt] = 0.f;

    int node = blockIdx.x * 8 + (threadIdx.x >> 5);
    int lane = threadIdx.x & 31;
    if (node >= NN) return;
    float4 acc = make_float4(0.f, 0.f, 0.f, 0.f);
#pragma unroll
    for (int f = 0; f < 9; f++) {
        int row = __ldg(&x[node * 9 + f]) + c_off[f];
        float4 v = *(const float4*)&table[row * HH + lane * 4];
        acc.x += v.x; acc.y += v.y; acc.z += v.z; acc.w += v.w;
    }
    *(float4*)&d_h[node * HH + lane * 4] = acc;
}

// ---------------- CSR construction ----------------
__global__ void degcount_kernel(const int* __restrict__ ei) {
    int e = blockIdx.x * blockDim.x + threadIdx.x;
    if (e < NE) atomicAdd(&d_cnt[ei[NE + e]], 1);
}

// scan1: per-block (1024 elems) inclusive scan of d_cnt -> d_rowptr, totals -> d_bsums
__global__ void scan1_kernel() {
    __shared__ int sh[256];
    int b = blockIdx.x;
    int base = b * 1024;
    int t = threadIdx.x;
    int v[4];
    int s = 0;
#pragma unroll
    for (int i = 0; i < 4; i++) {
        int idx = base + t * 4 + i;
        v[i] = (idx < NN) ? d_cnt[idx] : 0;
        s += v[i];
    }
    sh[t] = s;
    __syncthreads();
#pragma unroll
    for (int off = 1; off < 256; off <<= 1) {
        int x = (t >= off) ? sh[t - off] : 0;
        __syncthreads();
        sh[t] += x;
        __syncthreads();
    }
    int run = (t > 0) ? sh[t - 1] : 0;
#pragma unroll
    for (int i = 0; i < 4; i++) {
        run += v[i];
        int idx = base + t * 4 + i;
        if (idx < NN) d_rowptr[idx] = run;  // per-block inclusive
    }
    if (t == 255) d_bsums[b] = sh[255];
}

// scan2: exclusive scan of block sums (nb <= 128), single block of 128 threads
__global__ void scan2_kernel(int nb) {
    __shared__ int sh[128];
    int t = threadIdx.x;
    int v = (t < nb) ? d_bsums[t] : 0;
    sh[t] = v;
    __syncthreads();
#pragma unroll
    for (int off = 1; off < 128; off <<= 1) {
        int x = (t >= off) ? sh[t - off] : 0;
        __syncthreads();
        sh[t] += x;
        __syncthreads();
    }
    if (t < nb) d_bsums[t] = sh[t] - v;  // exclusive
}

// scan3: finalize exclusive rowptr, init cursor, compute dis
__global__ void scan3_kernel() {
    int i = blockIdx.x * blockDim.x + threadIdx.x;
    if (i < NN) {
        int b = i >> 10;
        int excl = d_rowptr[i] - d_cnt[i] + d_bsums[b];
        d_rowptr[i] = excl;
        d_cursor[i] = excl;
        d_dis[i] = rsqrtf((float)(d_cnt[i] + 1));  // +1 self loop
    }
    if (i == 0) d_rowptr[NN] = NE;
}

__global__ void fill_kernel(const int* __restrict__ ei) {
    int e = blockIdx.x * blockDim.x + threadIdx.x;
    if (e < NE) {
        int r = ei[e];
        int c = ei[NE + e];
        int p = atomicAdd(&d_cursor[c], 1);
        d_csr[p] = make_int2(r, __float_as_int(d_dis[r] * d_dis[c]));
    }
}

// ---------------- TF32 helpers ----------------
__device__ __forceinline__ unsigned f2tf32(float x) {
    unsigned r;
    asm("cvt.rna.tf32.f32 %0, %1;" : "=r"(r) : "f"(x));
    return r;
}

// one-shot: split all 5 layers' W into tf32 hi/lo (x = hi + lo to ~2^-24 rel)
__global__ void wsplit_kernel(const float* __restrict__ convW) {
    int i = blockIdx.x * blockDim.x + threadIdx.x;
    if (i >= LL * HH * HH) return;
    float w = convW[i];
    unsigned hi = f2tf32(w);
    d_Whi[i] = hi;
    d_Wlo[i] = f2tf32(w - __uint_as_float(hi));
}

// D(16x8) += A(16x8) * B(8x8), tf32 inputs, f32 accum.
// A row-major, B col-major (B[k][n] with b0=(k=tig,n=g), b1=(k=tig+4,n=g)).
__device__ __forceinline__ void mma_tf32(float* d, const unsigned* a, const unsigned* b) {
    asm volatile(
        "mma.sync.aligned.m16n8k8.row.col.f32.tf32.tf32.f32 "
        "{%0,%1,%2,%3}, {%4,%5,%6,%7}, {%8,%9}, {%0,%1,%2,%3};"
        : "+f"(d[0]), "+f"(d[1]), "+f"(d[2]), "+f"(d[3])
        : "r"(a[0]), "r"(a[1]), "r"(a[2]), "r"(a[3]), "r"(b[0]), "r"(b[1]));
}

// ---------------- GEMM (3xTF32 tensor cores + fused BN apply) ----------------
// d_ht[NN,128] = A[NN,128] * W_l[128,128], where
//   apply_bn==0: A = d_h (raw encoder output)
//   apply_bn==1: A = relu(fma(d_agg, scale, shift)) + d_h, also stored to d_h.
// 3xTF32 split: D = ah*bh + ah*bl + al*bh (al*bl ~2^-24 rel, dropped).
// Block 0 also zeroes the BN stat accumulators for the FOLLOWING agg_kernel.
// Warp grid 4(m) x 2(n): each warp owns 32 rows x 64 cols = 2x8 m16n8 tiles.
__global__ __launch_bounds__(256, 2) void gemm_kernel(int layer, int apply_bn) {
    __shared__ unsigned As_hi[2][8][136];   // [buf][k][row]
    __shared__ unsigned As_lo[2][8][136];
    __shared__ unsigned Ws_hi[2][8][132];   // [buf][k][n]
    __shared__ unsigned Ws_lo[2][8][132];

    const unsigned* __restrict__ Whi = d_Whi + layer * HH * HH;
    const unsigned* __restrict__ Wlo = d_Wlo + layer * HH * HH;

    int t = threadIdx.x;
    if (blockIdx.x == 0 && t < HH) {   // fold former zero_stats_kernel
        d_bnsum[t] = 0.f;
        d_bnsq[t] = 0.f;
    }
    int rowBase = blockIdx.x * 128;
    int warp = t >> 5;
    int lane = t & 31;
    int g   = lane >> 2;      // groupID
    int tig = lane & 3;       // thread-in-group
    int wm = warp & 3;        // m-position (32 rows each)
    int wn = warp >> 2;       // n-position (64 cols each)

    // staging coords
    int r  = t >> 1;              // row this thread stages
    int kq = (t & 1) * 4;         // k-quad within 8-wide chunk
    int grow = rowBase + r;
    bool rowOK = (grow < NN);
    int wk = t >> 5;              // W staging: k row
    int wn4 = (t & 31) * 4;       // W staging: n start (uint4)

    float acc[2][8][4];
#pragma unroll
    for (int mt = 0; mt < 2; mt++)
#pragma unroll
        for (int nt = 0; nt < 8; nt++)
#pragma unroll
            for (int i = 0; i < 4; i++) acc[mt][nt][i] = 0.f;

    auto load_chunk = [&](int k0, float4& va, uint4& whi, uint4& wlo) {
        va = make_float4(0.f, 0.f, 0.f, 0.f);
        if (rowOK) {
            int gidx = grow * 128 + k0 + kq;
            if (apply_bn) {
                float4 aa = *(const float4*)&d_agg[gidx];
                float4 hh = *(const float4*)&d_h[gidx];
                int c = k0 + kq;
                va.x = fmaxf(fmaf(aa.x, d_scale[c + 0], d_shift[c + 0]), 0.f) + hh.x;
                va.y = fmaxf(fmaf(aa.y, d_scale[c + 1], d_shift[c + 1]), 0.f) + hh.y;
                va.z = fmaxf(fmaf(aa.z, d_scale[c + 2], d_shift[c + 2]), 0.f) + hh.z;
                va.w = fmaxf(fmaf(aa.w, d_scale[c + 3], d_shift[c + 3]), 0.f) + hh.w;
                *(float4*)&d_h[gidx] = va;   // persist full-fp32 for next residual
            } else {
                va = *(const float4*)&d_h[gidx];
            }
        }
        int widx = (k0 + wk) * 128 + wn4;
        whi = *(const uint4*)&Whi[widx];
        wlo = *(const uint4*)&Wlo[widx];
    };
    auto store_chunk = [&](int buf, const float4& va, const uint4& whi, const uint4& wlo) {
        float av[4] = {va.x, va.y, va.z, va.w};
#pragma unroll
        for (int i = 0; i < 4; i++) {
            unsigned hi = f2tf32(av[i]);
            As_hi[buf][kq + i][r] = hi;
            As_lo[buf][kq + i][r] = f2tf32(av[i] - __uint_as_float(hi));
        }
        *(uint4*)&Ws_hi[buf][wk][wn4] = whi;
        *(uint4*)&Ws_lo[buf][wk][wn4] = wlo;
    };

    float4 va; uint4 whi, wlo;
    load_chunk(0, va, whi, wlo);
    store_chunk(0, va, whi, wlo);
    __syncthreads();

    for (int c = 0; c < 16; c++) {
        float4 nva; uint4 nwhi, nwlo;
        if (c < 15) load_chunk((c + 1) * 8, nva, nwhi, nwlo);
        int buf = c & 1;

        unsigned ah[2][4], al[2][4];
#pragma unroll
        for (int mt = 0; mt < 2; mt++) {
            int row = wm * 32 + mt * 16 + g;
            ah[mt][0] = As_hi[buf][tig][row];
            ah[mt][1] = As_hi[buf][tig][row + 8];
            ah[mt][2] = As_hi[buf][tig + 4][row];
            ah[mt][3] = As_hi[buf][tig + 4][row + 8];
            al[mt][0] = As_lo[buf][tig][row];
            al[mt][1] = As_lo[buf][tig][row + 8];
            al[mt][2] = As_lo[buf][tig + 4][row];
            al[mt][3] = As_lo[buf][tig + 4][row + 8];
        }
#pragma unroll
        for (int nt = 0; nt < 8; nt++) {
            int col = wn * 64 + nt * 8 + g;
            unsigned bh[2], bl[2];
            bh[0] = Ws_hi[buf][tig][col];
            bh[1] = Ws_hi[buf][tig + 4][col];
            bl[0] = Ws_lo[buf][tig][col];
            bl[1] = Ws_lo[buf][tig + 4][col];
#pragma unroll
            for (int mt = 0; mt < 2; mt++) {
                mma_tf32(acc[mt][nt], ah[mt], bh);
                mma_tf32(acc[mt][nt], ah[mt], bl);
                mma_tf32(acc[mt][nt], al[mt], bh);
            }
        }
        if (c < 15) {
            store_chunk((c + 1) & 1, nva, nwhi, nwlo);
            __syncthreads();
        }
    }

#pragma unroll
    for (int mt = 0; mt < 2; mt++) {
        int r0 = rowBase + wm * 32 + mt * 16 + g;
        int r1 = r0 + 8;
#pragma unroll
        for (int nt = 0; nt < 8; nt++) {
            int col = wn * 64 + nt * 8 + tig * 2;
            if (r0 < NN)
                *(float2*)&d_ht[r0 * 128 + col] = make_float2(acc[mt][nt][0], acc[mt][nt][1]);
            if (r1 < NN)
                *(float2*)&d_ht[r1 * 128 + col] = make_float2(acc[mt][nt][2], acc[mt][nt][3]);
        }
    }
}

// ---- aggregation + fused BN stats + fused BN-prep (last block) --------------
// agg[v] = ht[v]*dis[v]^2 + sum_in ht[src]*w. Packed CSR: one LDG.64 per edge,
// 4-way edge unroll (per-warp MLP ~6).
// BN stats: NO per-element atomics (round-15 post-mortem: 25.6M shared ATOMS
// per layer = ~190us/layer = the measured 1206us mystery). Instead each warp
// stores acc / acc^2 into sh[warp][132] (stride 132 -> bank (c+4w)%32, both
// write and read conflict-free), one syncthreads, then 128 threads tree-sum
// the 8 warp copies and issue only 256 global atomics per block.
// Threadfence reduction then elects the LAST block to compute scale/shift.
__global__ __launch_bounds__(256) void agg_kernel(const float* __restrict__ gamma,
                                                  const float* __restrict__ beta) {
    __shared__ float sh_v[8][132];
    __shared__ float sh_q[8][132];
    __shared__ bool sh_last;
    int t = threadIdx.x;
    int wid = t >> 5;
    int lane = t & 31;

    int v = blockIdx.x * 8 + wid;
    float d = d_dis[v];
    float sn = d * d;
    float4 self = *(const float4*)&d_ht[v * HH + lane * 4];
    float4 acc = make_float4(self.x * sn, self.y * sn, self.z * sn, self.w * sn);
    int s = d_rowptr[v], e = d_rowptr[v + 1];
    int j = s;
    for (; j + 3 < e; j += 4) {
        int2 e0 = d_csr[j];
        int2 e1 = d_csr[j + 1];
        int2 e2 = d_csr[j + 2];
        int2 e3 = d_csr[j + 3];
        float4 x0 = *(const float4*)&d_ht[e0.x * HH + lane * 4];
        float4 x1 = *(const float4*)&d_ht[e1.x * HH + lane * 4];
        float4 x2 = *(const float4*)&d_ht[e2.x * HH + lane * 4];
        float4 x3 = *(const float4*)&d_ht[e3.x * HH + lane * 4];
        float w0 = __int_as_float(e0.y);
        float w1 = __int_as_float(e1.y);
        float w2 = __int_as_float(e2.y);
        float w3 = __int_as_float(e3.y);
        acc.x = fmaf(x0.x, w0, acc.x); acc.y = fmaf(x0.y, w0, acc.y);
        acc.z = fmaf(x0.z, w0, acc.z); acc.w = fmaf(x0.w, w0, acc.w);
        acc.x = fmaf(x1.x, w1, acc.x); acc.y = fmaf(x1.y, w1, acc.y);
        acc.z = fmaf(x1.z, w1, acc.z); acc.w = fmaf(x1.w, w1, acc.w);
        acc.x = fmaf(x2.x, w2, acc.x); acc.y = fmaf(x2.y, w2, acc.y);
        acc.z = fmaf(x2.z, w2, acc.z); acc.w = fmaf(x2.w, w2, acc.w);
        acc.x = fmaf(x3.x, w3, acc.x); acc.y = fmaf(x3.y, w3, acc.y);
        acc.z = fmaf(x3.z, w3, acc.z); acc.w = fmaf(x3.w, w3, acc.w);
    }
    for (; j < e; j++) {
        int2 e0 = d_csr[j];
        float w = __int_as_float(e0.y);
        float4 xv = *(const float4*)&d_ht[e0.x * HH + lane * 4];
        acc.x = fmaf(xv.x, w, acc.x);
        acc.y = fmaf(xv.y, w, acc.y);
        acc.z = fmaf(xv.z, w, acc.z);
        acc.w = fmaf(xv.w, w, acc.w);
    }
    *(float4*)&d_agg[v * HH + lane * 4] = acc;

    // conflict-free per-warp store of values and squares (no atomics)
    int c = lane * 4;
    *(float4*)&sh_v[wid][c] = acc;
    *(float4*)&sh_q[wid][c] = make_float4(acc.x * acc.x, acc.y * acc.y,
                                          acc.z * acc.z, acc.w * acc.w);
    __syncthreads();
    if (t < 128) {
        float sv = 0.f, sq = 0.f;
#pragma unroll
        for (int w = 0; w < 8; w++) {
            sv += sh_v[w][t];
            sq += sh_q[w][t];
        }
        atomicAdd(&d_bnsum[t], sv);
        atomicAdd(&d_bnsq[t], sq);
    }

    // threadfence reduction: last block computes scale/shift
    __threadfence();
    __syncthreads();
    if (t == 0) {
        int done = atomicAdd(&d_aggdone, 1);
        sh_last = (done == NB_AGG - 1);
    }
    __syncthreads();
    if (sh_last) {
        if (t < HH) {
            const float inv = 1.0f / (float)NN;
            float m = d_bnsum[t] * inv;
            float var = d_bnsq[t] * inv - m * m;
            float sc = __ldg(&gamma[t]) * rsqrtf(var + BN_EPS);
            d_scale[t] = sc;
            d_shift[t] = __ldg(&beta[t]) - m * sc;
        }
        if (t == 0) d_aggdone = 0;   // reset for next layer / next graph replay
    }
}

// ---------------- readout ----------------
// batch_idx is SORTED: warp owns PCHUNK consecutive nodes, accumulates in
// registers, flushes atomics only on graph-id change (~66x fewer atomics).
// Fuses the LAST layer's BN apply (no relu): h_final = fma(agg,scale,shift)+h.
__global__ __launch_bounds__(256) void pool_kernel(const int* __restrict__ batch) {
    int w = blockIdx.x * 8 + (threadIdx.x >> 5);
    int lane = threadIdx.x & 31;
    int start = w * PCHUNK;
    if (start >= NN) return;
    int end = min(start + PCHUNK, NN);
    int c = lane * 4;
    float s0 = d_scale[c + 0], s1 = d_scale[c + 1], s2 = d_scale[c + 2], s3 = d_scale[c + 3];
    float b0 = d_shift[c + 0], b1 = d_shift[c + 1], b2 = d_shift[c + 2], b3 = d_shift[c + 3];
    int cur_g = __ldg(&batch[start]);
    float4 acc = make_float4(0.f, 0.f, 0.f, 0.f);
    float cnt = 0.f;
    for (int node = start; node < end; node++) {
        int g = __ldg(&batch[node]);   // broadcast load, uniform across warp
        if (g != cur_g) {
            float* base = &d_gsum[cur_g * HH + c];
            atomicAdd(base + 0, acc.x);
            atomicAdd(base + 1, acc.y);
            atomicAdd(base + 2, acc.z);
            atomicAdd(base + 3, acc.w);
            if (lane == 0) atomicAdd(&d_gcnt[cur_g], cnt);
            acc = make_float4(0.f, 0.f, 0.f, 0.f);
            cnt = 0.f;
            cur_g = g;
        }
        int idx = node * HH + c;
        float4 aa = *(const float4*)&d_agg[idx];
        float4 hh = *(const float4*)&d_h[idx];
        acc.x += fmaf(aa.x, s0, b0) + hh.x;
        acc.y += fmaf(aa.y, s1, b1) + hh.y;
        acc.z += fmaf(aa.z, s2, b2) + hh.z;
        acc.w += fmaf(aa.w, s3, b3) + hh.w;
        cnt += 1.f;
    }
    float* base = &d_gsum[cur_g * HH + c];
    atomicAdd(base + 0, acc.x);
    atomicAdd(base + 1, acc.y);
    atomicAdd(base + 2, acc.z);
    atomicAdd(base + 3, acc.w);
    if (lane == 0) atomicAdd(&d_gcnt[cur_g], cnt);
}

__global__ void final_kernel(const float* __restrict__ linW, const float* __restrict__ linb,
                             float* __restrict__ out) {
    int g = blockIdx.x * 8 + (threadIdx.x >> 5);
    int lane = threadIdx.x & 31;
    if (g >= GG) return;
    float4 s = *(const float4*)&d_gsum[g * HH + lane * 4];
    float4 w = *(const float4*)&linW[lane * 4];
    float dot = s.x * w.x + s.y * w.y + s.z * w.z + s.w * w.w;
#pragma unroll
    for (int off = 16; off; off >>= 1) dot += __shfl_xor_sync(0xffffffff, dot, off);
    if (lane == 0) {
        float cnt = fmaxf(d_gcnt[g], 1.f);
        float z = dot / cnt + __ldg(&linb[0]);
        out[g] = 1.f / (1.f + expf(-z));
    }
}

// ---------------- launch ----------------
extern "C" void kernel_launch(void* const* d_in, const int* in_sizes, int n_in,
                              void* d_out, int out_size) {
    const int*   x     = (const int*)d_in[0];
    const int*   ei    = (const int*)d_in[1];
    const int*   batch = (const int*)d_in[2];
    const float* table = (const float*)d_in[3];
    const float* convW = (const float*)d_in[4];
    // d_in[5] = conv_b: cancels exactly under training-mode BatchNorm -> unused
    const float* gamma = (const float*)d_in[6];
    const float* beta  = (const float*)d_in[7];
    const float* linW  = (const float*)d_in[8];
    const float* linb  = (const float*)d_in[9];
    float* out = (float*)d_out;

    const int NB_NODE_W = (NN + 7) / 8;          // 12500
    const int NB_EDGE   = (NE + 255) / 256;      // 2344
    const int NB_SCAN   = (NN + 1023) / 1024;    // 98
    const int NB_ELEM   = (NN + 255) / 256;      // 391
    const int NB_GEMM   = (NN + 127) / 128;      // 782
    const int NB_POOL   = (NN / PCHUNK + 7) / 8; // 125

    // encoder (also zeroes d_cnt + pool accumulators) + weight split
    encode_kernel<<<NB_NODE_W, 256>>>(x, table);
    wsplit_kernel<<<(LL * HH * HH + 255) / 256, 256>>>(convW);
    degcount_kernel<<<NB_EDGE, 256>>>(ei);

    // layer-0 GEMM hoisted before the CSR scan chain (depends only on
    // encode + wsplit) -> lands in ncu's captured launch slot for profiling.
    gemm_kernel<<<NB_GEMM, 256>>>(0, 0);

    // CSR build + norms (needed from agg0 onward)
    scan1_kernel<<<NB_SCAN, 256>>>();
    scan2_kernel<<<1, 128>>>(NB_SCAN);
    scan3_kernel<<<NB_ELEM, 256>>>();
    fill_kernel<<<NB_EDGE, 256>>>(ei);

    agg_kernel<<<NB_AGG, 256>>>(gamma, beta);
    for (int l = 1; l < LL; l++) {
        gemm_kernel<<<NB_GEMM, 256>>>(l, 1);
        agg_kernel<<<NB_AGG, 256>>>(gamma + l * HH, beta + l * HH);
    }

    // readout (fuses layer-4 BN apply, no relu)
    pool_kernel<<<NB_POOL, 256>>>(batch);
    final_kernel<<<(GG + 7) / 8, 256>>>(linW, linb, out);
}